// round 4
// baseline (speedup 1.0000x reference)
#include <cuda_runtime.h>

#define NN 10000
#define EE 640000

// ---- device scratch (static; no allocations) ----
__device__ float d_AB[NN * 256];      // A = x@W1a (cols 0..127), Bb = x@W1b + b1 (cols 128..255)
__device__ float d_H[NN * 128];       // aggregated relu sums
__device__ float d_Wp[128 * 256];     // packed W1
__device__ float d_bias256[256];      // 0 for cols<128, b1 for cols>=128
__device__ int   d_deg[NN];
__device__ int   d_off[NN + 1];
__device__ int   d_cur[NN];
__device__ int   d_eidx[EE];
__device__ int   d_shift;             // 0: edge_index is int32, 1: int64

// ---- detect edge_index dtype: int64 has zero high words for values < 2^31 ----
__global__ void detect_kernel(const int* __restrict__ eiw) {
    int t = threadIdx.x;                       // 32 threads
    int v = eiw[2 * t + 1];                    // odd words of first 32 entries (if int64)
    unsigned mask = __ballot_sync(0xFFFFFFFFu, v == 0);
    if (t == 0) d_shift = (mask == 0xFFFFFFFFu) ? 1 : 0;
}

// ---- pack W1 into fused layout + bias vector; also zero deg ----
__global__ void pack_kernel(const float* __restrict__ W1, const float* __restrict__ b1) {
    int idx = blockIdx.x * 256 + threadIdx.x;  // 0..32767
    if (idx < 128 * 256) {
        int k = idx >> 8, j = idx & 255;
        d_Wp[idx] = (j < 128) ? W1[k * 128 + j] : W1[(128 + k) * 128 + (j - 128)];
    }
    if (idx < 256) d_bias256[idx] = (idx < 128) ? 0.f : b1[idx - 128];
    if (idx < NN) d_deg[idx] = 0;
}

__global__ void hist_kernel(const int* __restrict__ eiw) {
    int e = blockIdx.x * 256 + threadIdx.x;
    if (e < EE) {
        int s = d_shift;
        int c = eiw[(EE + e) << s];
        if (c >= 0 && c < NN) atomicAdd(&d_deg[c], 1);
    }
}

// 256-thread single-block exclusive scan over deg[NN] -> off, cur (two-pass, no local arrays)
__global__ void scan_kernel() {
    __shared__ int sh[256];
    const int C = (NN + 255) / 256;            // 40
    int t = threadIdx.x;
    int base = t * C;
    int s = 0;
    for (int i = 0; i < C; i++) {
        int idx = base + i;
        if (idx < NN) s += d_deg[idx];
    }
    sh[t] = s;
    __syncthreads();
    for (int d = 1; d < 256; d <<= 1) {
        int v = (t >= d) ? sh[t - d] : 0;
        __syncthreads();
        sh[t] += v;
        __syncthreads();
    }
    int run = sh[t] - s;                       // exclusive prefix for this thread's chunk
    for (int i = 0; i < C; i++) {
        int idx = base + i;
        if (idx < NN) {
            d_off[idx] = run;
            d_cur[idx] = run;
            run += d_deg[idx];
        }
    }
    if (t == 255) d_off[NN] = sh[255];
}

__global__ void fill_kernel(const int* __restrict__ eiw) {
    int e = blockIdx.x * 256 + threadIdx.x;
    if (e < EE) {
        int s = d_shift;
        int c = eiw[(EE + e) << s];
        if (c >= 0 && c < NN) {
            int p = atomicAdd(&d_cur[c], 1);
            d_eidx[p] = e;
        }
    }
}

// ---- SGEMM: 64x64 tile, 256 threads, 4x4 microtile, scalar shared accesses ----
// d_AB = X @ Wp + bias256   (M=NN, K=128, N=256)
__global__ void __launch_bounds__(256) gemm1_kernel(const float* __restrict__ X) {
    __shared__ float Xs[64 * 17];   // [row][k] padded
    __shared__ float Ws[16 * 65];   // [k][col] padded
    int bm = blockIdx.y * 64, bn = blockIdx.x * 64;
    int t = threadIdx.x;
    int tr = t >> 4, tc = t & 15;
    float acc[4][4];
#pragma unroll
    for (int i = 0; i < 4; i++)
#pragma unroll
        for (int j = 0; j < 4; j++) acc[i][j] = 0.f;

    for (int k0 = 0; k0 < 128; k0 += 16) {
#pragma unroll
        for (int u = 0; u < 4; u++) {
            int idx = t * 4 + u;
            int r = idx >> 4, kk = idx & 15;
            int gr = bm + r;
            Xs[r * 17 + kk] = (gr < NN) ? X[gr * 128 + k0 + kk] : 0.f;
        }
#pragma unroll
        for (int u = 0; u < 4; u++) {
            int idx = t * 4 + u;
            int kk = idx >> 6, c = idx & 63;
            Ws[kk * 65 + c] = d_Wp[(k0 + kk) * 256 + bn + c];
        }
        __syncthreads();
#pragma unroll
        for (int kk = 0; kk < 16; kk++) {
            float av0 = Xs[(tr * 4 + 0) * 17 + kk];
            float av1 = Xs[(tr * 4 + 1) * 17 + kk];
            float av2 = Xs[(tr * 4 + 2) * 17 + kk];
            float av3 = Xs[(tr * 4 + 3) * 17 + kk];
            float bv0 = Ws[kk * 65 + tc * 4 + 0];
            float bv1 = Ws[kk * 65 + tc * 4 + 1];
            float bv2 = Ws[kk * 65 + tc * 4 + 2];
            float bv3 = Ws[kk * 65 + tc * 4 + 3];
            acc[0][0] = fmaf(av0, bv0, acc[0][0]); acc[0][1] = fmaf(av0, bv1, acc[0][1]);
            acc[0][2] = fmaf(av0, bv2, acc[0][2]); acc[0][3] = fmaf(av0, bv3, acc[0][3]);
            acc[1][0] = fmaf(av1, bv0, acc[1][0]); acc[1][1] = fmaf(av1, bv1, acc[1][1]);
            acc[1][2] = fmaf(av1, bv2, acc[1][2]); acc[1][3] = fmaf(av1, bv3, acc[1][3]);
            acc[2][0] = fmaf(av2, bv0, acc[2][0]); acc[2][1] = fmaf(av2, bv1, acc[2][1]);
            acc[2][2] = fmaf(av2, bv2, acc[2][2]); acc[2][3] = fmaf(av2, bv3, acc[2][3]);
            acc[3][0] = fmaf(av3, bv0, acc[3][0]); acc[3][1] = fmaf(av3, bv1, acc[3][1]);
            acc[3][2] = fmaf(av3, bv2, acc[3][2]); acc[3][3] = fmaf(av3, bv3, acc[3][3]);
        }
        __syncthreads();
    }
#pragma unroll
    for (int i = 0; i < 4; i++) {
        int gr = bm + tr * 4 + i;
        if (gr < NN) {
#pragma unroll
            for (int j = 0; j < 4; j++) {
                int gc = bn + tc * 4 + j;
                d_AB[gr * 256 + gc] = acc[i][j] + d_bias256[gc];
            }
        }
    }
}

// ---- per-node gather aggregation: H[c] = sum_e relu(ea_e * A[row_e] + Bb[c]) ----
__global__ void __launch_bounds__(128) agg_kernel(const int* __restrict__ eiw,
                                                  const float* __restrict__ ea) {
    int c = blockIdx.x;
    int ch = threadIdx.x;  // 128 threads = channels
    int s = d_shift;
    float bc = d_AB[c * 256 + 128 + ch];
    int start = d_off[c], end = d_off[c + 1];
    __shared__ int srow[128];
    __shared__ float sea[128];
    float acc = 0.f;
    for (int base = start; base < end; base += 128) {
        int n = min(128, end - base);
        if (ch < n) {
            int e = d_eidx[base + ch];
            int r = eiw[e << s];
            srow[ch] = (r >= 0 && r < NN) ? r : 0;
            sea[ch] = ea[e];
        }
        __syncthreads();
        int i = 0;
        for (; i + 4 <= n; i += 4) {
            float a0 = d_AB[srow[i]     * 256 + ch];
            float a1 = d_AB[srow[i + 1] * 256 + ch];
            float a2 = d_AB[srow[i + 2] * 256 + ch];
            float a3 = d_AB[srow[i + 3] * 256 + ch];
            acc += fmaxf(fmaf(sea[i],     a0, bc), 0.f);
            acc += fmaxf(fmaf(sea[i + 1], a1, bc), 0.f);
            acc += fmaxf(fmaf(sea[i + 2], a2, bc), 0.f);
            acc += fmaxf(fmaf(sea[i + 3], a3, bc), 0.f);
        }
        for (; i < n; i++)
            acc += fmaxf(fmaf(sea[i], d_AB[srow[i] * 256 + ch], bc), 0.f);
        __syncthreads();
    }
    d_H[c * 128 + ch] = acc;
}

// ---- out = H @ W2 + deg[n]*b2   (M=NN, K=128, N=128) ----
__global__ void __launch_bounds__(256) gemm2_kernel(const float* __restrict__ W2,
                                                    const float* __restrict__ b2,
                                                    float* __restrict__ out) {
    __shared__ float Xs[64 * 17];
    __shared__ float Ws[16 * 65];
    int bm = blockIdx.y * 64, bn = blockIdx.x * 64;
    int t = threadIdx.x;
    int tr = t >> 4, tc = t & 15;
    float acc[4][4];
#pragma unroll
    for (int i = 0; i < 4; i++)
#pragma unroll
        for (int j = 0; j < 4; j++) acc[i][j] = 0.f;

    for (int k0 = 0; k0 < 128; k0 += 16) {
#pragma unroll
        for (int u = 0; u < 4; u++) {
            int idx = t * 4 + u;
            int r = idx >> 4, kk = idx & 15;
            int gr = bm + r;
            Xs[r * 17 + kk] = (gr < NN) ? d_H[gr * 128 + k0 + kk] : 0.f;
        }
#pragma unroll
        for (int u = 0; u < 4; u++) {
            int idx = t * 4 + u;
            int kk = idx >> 6, c = idx & 63;
            Ws[kk * 65 + c] = W2[(k0 + kk) * 128 + bn + c];
        }
        __syncthreads();
#pragma unroll
        for (int kk = 0; kk < 16; kk++) {
            float av0 = Xs[(tr * 4 + 0) * 17 + kk];
            float av1 = Xs[(tr * 4 + 1) * 17 + kk];
            float av2 = Xs[(tr * 4 + 2) * 17 + kk];
            float av3 = Xs[(tr * 4 + 3) * 17 + kk];
            float bv0 = Ws[kk * 65 + tc * 4 + 0];
            float bv1 = Ws[kk * 65 + tc * 4 + 1];
            float bv2 = Ws[kk * 65 + tc * 4 + 2];
            float bv3 = Ws[kk * 65 + tc * 4 + 3];
            acc[0][0] = fmaf(av0, bv0, acc[0][0]); acc[0][1] = fmaf(av0, bv1, acc[0][1]);
            acc[0][2] = fmaf(av0, bv2, acc[0][2]); acc[0][3] = fmaf(av0, bv3, acc[0][3]);
            acc[1][0] = fmaf(av1, bv0, acc[1][0]); acc[1][1] = fmaf(av1, bv1, acc[1][1]);
            acc[1][2] = fmaf(av1, bv2, acc[1][2]); acc[1][3] = fmaf(av1, bv3, acc[1][3]);
            acc[2][0] = fmaf(av2, bv0, acc[2][0]); acc[2][1] = fmaf(av2, bv1, acc[2][1]);
            acc[2][2] = fmaf(av2, bv2, acc[2][2]); acc[2][3] = fmaf(av2, bv3, acc[2][3]);
            acc[3][0] = fmaf(av3, bv0, acc[3][0]); acc[3][1] = fmaf(av3, bv1, acc[3][1]);
            acc[3][2] = fmaf(av3, bv2, acc[3][2]); acc[3][3] = fmaf(av3, bv3, acc[3][3]);
        }
        __syncthreads();
    }
#pragma unroll
    for (int i = 0; i < 4; i++) {
        int gr = bm + tr * 4 + i;
        if (gr < NN) {
            float degf = (float)d_deg[gr];
#pragma unroll
            for (int j = 0; j < 4; j++) {
                int gc = bn + tc * 4 + j;
                out[gr * 128 + gc] = acc[i][j] + degf * b2[gc];
            }
        }
    }
}

extern "C" void kernel_launch(void* const* d_in, const int* in_sizes, int n_in,
                              void* d_out, int out_size) {
    const float* x   = (const float*)d_in[0];
    const int*   eiw = (const int*)d_in[1];   // edge_index as 32-bit words (int32 or int64 halves)
    const float* ea  = (const float*)d_in[2];
    const float* W1  = (const float*)d_in[3];
    const float* b1  = (const float*)d_in[4];
    const float* W2  = (const float*)d_in[5];
    const float* b2  = (const float*)d_in[6];
    float* out = (float*)d_out;

    detect_kernel<<<1, 32>>>(eiw);
    pack_kernel<<<128, 256>>>(W1, b1);
    hist_kernel<<<(EE + 255) / 256, 256>>>(eiw);
    scan_kernel<<<1, 256>>>();
    fill_kernel<<<(EE + 255) / 256, 256>>>(eiw);
    gemm1_kernel<<<dim3(4, 157), 256>>>(x);
    agg_kernel<<<NN, 128>>>(eiw, ea);
    gemm2_kernel<<<dim3(2, 157), 256>>>(W2, b2, out);
}

// round 5
// speedup vs baseline: 1.0612x; 1.0612x over previous
#include <cuda_runtime.h>
#include <cuda_bf16.h>

#define NN 10000
#define EE 640000

// ---- device scratch (static; no allocations) ----
__device__ __nv_bfloat16 d_Abf[NN * 128];  // A = x@W1a, bf16 (gathered operand)
__device__ float d_Bb[NN * 128];           // Bb = x@W1b + b1, fp32
__device__ float d_H[NN * 128];            // aggregated relu sums
__device__ int   d_deg[NN];
__device__ int   d_off[NN + 1];
__device__ int   d_cur[NN];
__device__ int   d_eidx[EE];
__device__ int   d_shift;                  // 0: edge_index is int32, 1: int64

// ---- zero deg everywhere; block 0 warp 0 detects edge_index dtype ----
__global__ void init_kernel(const int* __restrict__ eiw) {
    int i = blockIdx.x * 256 + threadIdx.x;
    if (i < NN) d_deg[i] = 0;
    if (blockIdx.x == 0 && threadIdx.x < 32) {
        int t = threadIdx.x;
        int v = eiw[2 * t + 1];  // odd words of first 32 entries (zero if int64, values < 2^31)
        unsigned mask = __ballot_sync(0xFFFFFFFFu, v == 0);
        if (t == 0) d_shift = (mask == 0xFFFFFFFFu) ? 1 : 0;
    }
}

__global__ void hist_kernel(const int* __restrict__ eiw) {
    int e = blockIdx.x * 256 + threadIdx.x;
    if (e < EE) {
        int s = d_shift;
        int c = eiw[(EE + e) << s];
        if (c >= 0 && c < NN) atomicAdd(&d_deg[c], 1);
    }
}

// 1024-thread single-block exclusive scan over deg[NN] -> off, cur
__global__ void __launch_bounds__(1024) scan_kernel() {
    __shared__ int sh[1024];
    const int C = (NN + 1023) / 1024;  // 10
    int t = threadIdx.x;
    int base = t * C;
    int s = 0;
    for (int i = 0; i < C; i++) {
        int idx = base + i;
        if (idx < NN) s += d_deg[idx];
    }
    sh[t] = s;
    __syncthreads();
    for (int d = 1; d < 1024; d <<= 1) {
        int v = (t >= d) ? sh[t - d] : 0;
        __syncthreads();
        sh[t] += v;
        __syncthreads();
    }
    int run = sh[t] - s;
    for (int i = 0; i < C; i++) {
        int idx = base + i;
        if (idx < NN) {
            d_off[idx] = run;
            d_cur[idx] = run;
            run += d_deg[idx];
        }
    }
    if (t == 1023) d_off[NN] = sh[1023];
}

__global__ void fill_kernel(const int* __restrict__ eiw) {
    int e = blockIdx.x * 256 + threadIdx.x;
    if (e < EE) {
        int s = d_shift;
        int c = eiw[(EE + e) << s];
        if (c >= 0 && c < NN) {
            int p = atomicAdd(&d_cur[c], 1);
            d_eidx[p] = e;
        }
    }
}

// ---- gemm1: 128x64 tile, 256 threads, 8x4 microtile, float4 shared loads ----
// computes X @ [W1a | W1b]; A half -> bf16 d_Abf, B half + b1 -> fp32 d_Bb
__global__ void __launch_bounds__(256) gemm1_kernel(const float* __restrict__ X,
                                                    const float* __restrict__ W1,
                                                    const float* __restrict__ b1) {
    __shared__ __align__(16) float Xs[16 * 132];  // [kk][row], padded
    __shared__ __align__(16) float Ws[16 * 68];   // [kk][col], padded
    int bm = blockIdx.y * 128, bn = blockIdx.x * 64;
    int t = threadIdx.x;
    int tr = t >> 4, tc = t & 15;  // 16x16 threads; rows tr*8..+7, cols tc*4..+3
    float acc[8][4];
#pragma unroll
    for (int i = 0; i < 8; i++)
#pragma unroll
        for (int j = 0; j < 4; j++) acc[i][j] = 0.f;

    for (int k0 = 0; k0 < 128; k0 += 16) {
#pragma unroll
        for (int u = 0; u < 8; u++) {
            int idx = t * 8 + u;              // 0..2047
            int r = idx >> 4, kk = idx & 15;
            int gr = bm + r;
            Xs[kk * 132 + r] = (gr < NN) ? X[gr * 128 + k0 + kk] : 0.f;
        }
#pragma unroll
        for (int u = 0; u < 4; u++) {
            int idx = t * 4 + u;              // 0..1023
            int kk = idx >> 6, c = idx & 63;
            int gc = bn + c;
            Ws[kk * 68 + c] = (gc < 128) ? W1[(k0 + kk) * 128 + gc]
                                         : W1[(128 + k0 + kk) * 128 + (gc - 128)];
        }
        __syncthreads();
#pragma unroll
        for (int kk = 0; kk < 16; kk++) {
            float4 a0 = *(const float4*)&Xs[kk * 132 + tr * 8];
            float4 a1 = *(const float4*)&Xs[kk * 132 + tr * 8 + 4];
            float4 b0 = *(const float4*)&Ws[kk * 68 + tc * 4];
            float av[8] = {a0.x, a0.y, a0.z, a0.w, a1.x, a1.y, a1.z, a1.w};
            float bv[4] = {b0.x, b0.y, b0.z, b0.w};
#pragma unroll
            for (int i = 0; i < 8; i++)
#pragma unroll
                for (int j = 0; j < 4; j++) acc[i][j] = fmaf(av[i], bv[j], acc[i][j]);
        }
        __syncthreads();
    }
#pragma unroll
    for (int i = 0; i < 8; i++) {
        int gr = bm + tr * 8 + i;
        if (gr < NN) {
#pragma unroll
            for (int j = 0; j < 4; j++) {
                int gc = bn + tc * 4 + j;
                if (gc < 128) d_Abf[gr * 128 + gc] = __float2bfloat16(acc[i][j]);
                else          d_Bb[gr * 128 + (gc - 128)] = acc[i][j] + b1[gc - 128];
            }
        }
    }
}

// ---- per-node gather: H[c] = sum_e relu(ea_e * A[row_e] + Bb[c]) ----
__global__ void __launch_bounds__(128) agg_kernel(const int* __restrict__ eiw,
                                                  const float* __restrict__ ea) {
    int c = blockIdx.x;
    int ch = threadIdx.x;  // 128 threads = channels
    int s = d_shift;
    float bc = d_Bb[c * 128 + ch];
    int start = d_off[c], end = d_off[c + 1];
    __shared__ int srow[128];
    __shared__ float sea[128];
    float acc = 0.f;
    for (int base = start; base < end; base += 128) {
        int n = min(128, end - base);
        if (ch < n) {
            int e = d_eidx[base + ch];
            int r = eiw[e << s];
            srow[ch] = (r >= 0 && r < NN) ? r : 0;
            sea[ch] = ea[e];
        }
        __syncthreads();
        int i = 0;
        for (; i + 8 <= n; i += 8) {
            float a0 = __bfloat162float(d_Abf[srow[i]     * 128 + ch]);
            float a1 = __bfloat162float(d_Abf[srow[i + 1] * 128 + ch]);
            float a2 = __bfloat162float(d_Abf[srow[i + 2] * 128 + ch]);
            float a3 = __bfloat162float(d_Abf[srow[i + 3] * 128 + ch]);
            float a4 = __bfloat162float(d_Abf[srow[i + 4] * 128 + ch]);
            float a5 = __bfloat162float(d_Abf[srow[i + 5] * 128 + ch]);
            float a6 = __bfloat162float(d_Abf[srow[i + 6] * 128 + ch]);
            float a7 = __bfloat162float(d_Abf[srow[i + 7] * 128 + ch]);
            acc += fmaxf(fmaf(sea[i],     a0, bc), 0.f);
            acc += fmaxf(fmaf(sea[i + 1], a1, bc), 0.f);
            acc += fmaxf(fmaf(sea[i + 2], a2, bc), 0.f);
            acc += fmaxf(fmaf(sea[i + 3], a3, bc), 0.f);
            acc += fmaxf(fmaf(sea[i + 4], a4, bc), 0.f);
            acc += fmaxf(fmaf(sea[i + 5], a5, bc), 0.f);
            acc += fmaxf(fmaf(sea[i + 6], a6, bc), 0.f);
            acc += fmaxf(fmaf(sea[i + 7], a7, bc), 0.f);
        }
        for (; i < n; i++)
            acc += fmaxf(fmaf(sea[i], __bfloat162float(d_Abf[srow[i] * 128 + ch]), bc), 0.f);
        __syncthreads();
    }
    d_H[c * 128 + ch] = acc;
}

// ---- gemm2: out = H @ W2 + deg[n]*b2 ; 128x64 tile, 8x4 microtile ----
__global__ void __launch_bounds__(256) gemm2_kernel(const float* __restrict__ W2,
                                                    const float* __restrict__ b2,
                                                    float* __restrict__ out) {
    __shared__ __align__(16) float Xs[16 * 132];
    __shared__ __align__(16) float Ws[16 * 68];
    int bm = blockIdx.y * 128, bn = blockIdx.x * 64;
    int t = threadIdx.x;
    int tr = t >> 4, tc = t & 15;
    float acc[8][4];
#pragma unroll
    for (int i = 0; i < 8; i++)
#pragma unroll
        for (int j = 0; j < 4; j++) acc[i][j] = 0.f;

    for (int k0 = 0; k0 < 128; k0 += 16) {
#pragma unroll
        for (int u = 0; u < 8; u++) {
            int idx = t * 8 + u;
            int r = idx >> 4, kk = idx & 15;
            int gr = bm + r;
            Xs[kk * 132 + r] = (gr < NN) ? d_H[gr * 128 + k0 + kk] : 0.f;
        }
#pragma unroll
        for (int u = 0; u < 4; u++) {
            int idx = t * 4 + u;
            int kk = idx >> 6, c = idx & 63;
            Ws[kk * 68 + c] = W2[(k0 + kk) * 128 + bn + c];
        }
        __syncthreads();
#pragma unroll
        for (int kk = 0; kk < 16; kk++) {
            float4 a0 = *(const float4*)&Xs[kk * 132 + tr * 8];
            float4 a1 = *(const float4*)&Xs[kk * 132 + tr * 8 + 4];
            float4 b0 = *(const float4*)&Ws[kk * 68 + tc * 4];
            float av[8] = {a0.x, a0.y, a0.z, a0.w, a1.x, a1.y, a1.z, a1.w};
            float bv[4] = {b0.x, b0.y, b0.z, b0.w};
#pragma unroll
            for (int i = 0; i < 8; i++)
#pragma unroll
                for (int j = 0; j < 4; j++) acc[i][j] = fmaf(av[i], bv[j], acc[i][j]);
        }
        __syncthreads();
    }
#pragma unroll
    for (int i = 0; i < 8; i++) {
        int gr = bm + tr * 8 + i;
        if (gr < NN) {
            float degf = (float)d_deg[gr];
#pragma unroll
            for (int j = 0; j < 4; j++) {
                int gc = bn + tc * 4 + j;
                out[gr * 128 + gc] = acc[i][j] + degf * b2[gc];
            }
        }
    }
}

extern "C" void kernel_launch(void* const* d_in, const int* in_sizes, int n_in,
                              void* d_out, int out_size) {
    const float* x   = (const float*)d_in[0];
    const int*   eiw = (const int*)d_in[1];   // edge_index as 32-bit words
    const float* ea  = (const float*)d_in[2];
    const float* W1  = (const float*)d_in[3];
    const float* b1  = (const float*)d_in[4];
    const float* W2  = (const float*)d_in[5];
    const float* b2  = (const float*)d_in[6];
    float* out = (float*)d_out;

    init_kernel<<<(NN + 255) / 256, 256>>>(eiw);
    gemm1_kernel<<<dim3(4, 79), 256>>>(x, W1, b1);
    hist_kernel<<<(EE + 255) / 256, 256>>>(eiw);
    scan_kernel<<<1, 1024>>>();
    fill_kernel<<<(EE + 255) / 256, 256>>>(eiw);
    agg_kernel<<<NN, 128>>>(eiw, ea);
    gemm2_kernel<<<dim3(2, 79), 256>>>(W2, b2, out);
}